// round 8
// baseline (speedup 1.0000x reference)
#include <cuda_runtime.h>

#define N 160
#define NP1 161
#define TWO_N 320
#define NCELLS (N * N)
#define BC 512
#define CH 8
#define BATCH 64
#define BIGV 1e10f
#define GAMMA 0.01f
#define INVG 100.0f

// Scratch: softmin gradient weights per cell, diag-major, SoA (coalesced).
__device__ float g_wd[(size_t)BC * NCELLS];  // diag-parent weight
__device__ float g_wu[(size_t)BC * NCELLS];  // up-parent weight
__device__ float g_wl[(size_t)BC * NCELLS];  // left-parent weight
__device__ float g_sdtw[BC];
__device__ float g_lt[BC];

// Offset of anti-diagonal e (e = i + j, cells 1-based, e in [2, 2N]) in
// diag-major cell ordering.
__device__ __forceinline__ int diag_off(int e) {
    return (e <= N + 1) ? ((e - 2) * (e - 1)) / 2
                        : NCELLS - ((TWO_N + 1 - e) * (TWO_N + 2 - e)) / 2;
}

__global__ __launch_bounds__(160) void dtw_fwd_bwd_kernel(
    const float* __restrict__ input, const float* __restrict__ target) {
    const int prob = blockIdx.x;   // 0..511  (b*C + c)
    const int tid = threadIdx.x;   // 0..159

    __shared__ float sp[N];        // input row  (columns j of D)
    __shared__ float st[N];        // target row (rows i of D)
    __shared__ float Rb[3][NP1];   // rotating R diagonals, indexed by absolute j
    __shared__ float Eb[3][NP1 + 2];
    __shared__ int doff[TWO_N + 3];
    __shared__ float warp_sum[5];
    __shared__ float s_sdtw;

    sp[tid] = input[prob * N + tid];
    st[tid] = target[prob * N + tid];
    for (int e = tid + 2; e <= TWO_N + 2; e += 160)
        doff[e] = (e <= TWO_N) ? diag_off(e) : 0;

    if (tid == 0) {
        Rb[0][0] = 0.0f;   // R[0,0]
        Rb[1][0] = BIGV;   // R[1,0]
        Rb[1][1] = BIGV;   // R[0,1]
    }
    __syncthreads();

    const int pb = prob * NCELLS;

    // ---------------- forward: R + stash softmin weights ----------------
    for (int e = 2; e <= TWO_N; ++e) {
        const int cur = e % 3;
        const int b1 = (e + 2) % 3;  // diag e-1
        const int b2 = (e + 1) % 3;  // diag e-2
        const int j = tid + 1;
        const int jmin = max(1, e - N);
        const int jmax = min(N, e - 1);
        if (j >= jmin && j <= jmax) {
            const int i = e - j;
            float d = st[i - 1] - sp[j - 1];
            d *= d;
            const float a = Rb[b2][j - 1];  // diag parent R[i-1,j-1]
            const float b = Rb[b1][j];      // up   parent R[i-1,j]
            const float c = Rb[b1][j - 1];  // left parent R[i,j-1]
            // exact 3-element sorting network (FMNMX only)
            const float lo = fminf(a, b);
            const float hi = fmaxf(a, b);
            const float mn = fminf(lo, c);
            const float md = fminf(hi, fmaxf(lo, c));
            const float mx = fmaxf(hi, c);
            // softmin: min slot contributes exp(0)=1 -> only 2 exps needed
            const float e1 = __expf((mn - md) * INVG);
            const float e2 = __expf((mn - mx) * INVG);
            const float s = 1.0f + e1 + e2;
            const float r = d + mn - GAMMA * __logf(s);
            Rb[cur][j] = r;
            const float inv = __fdividef(1.0f, s);
            const float w1 = e1 * inv;
            const float w2 = e2 * inv;
            // map each parent back to its weight via exact equality selects
            const float wa = (a == mn) ? inv : ((a == md) ? w1 : w2);
            const float wb = (b == mn) ? inv : ((b == md) ? w1 : w2);
            const float wc = (c == mn) ? inv : ((c == md) ? w1 : w2);
            const int o = pb + doff[e] + (j - jmin);
            g_wd[o] = wa;
            g_wu[o] = wb;
            g_wl[o] = wc;
            if (e == TWO_N) s_sdtw = r;  // only j==N active here
        }
        if (tid == 0) {
            Rb[cur][0] = BIGV;              // R[e,0]
            if (e <= N) Rb[cur][e] = BIGV;  // R[0,e]
        }
        __syncthreads();
    }

    // ---------------- backward: E recursion, accumulate temporal ----------------
    float acc = 0.0f;
    for (int e = TWO_N; e >= 2; --e) {
        const int cur = e % 3;
        const int p1 = (e + 1) % 3;  // diag e+1
        const int p2 = (e + 2) % 3;  // diag e+2
        const int j = tid + 1;
        const int jmin = max(1, e - N);
        const int jmax = min(N, e - 1);
        if (j >= jmin && j <= jmax) {
            const int i = e - j;
            float Eij;
            if (e == TWO_N) {
                Eij = 1.0f;
            } else {
                Eij = 0.0f;
                const int jmin1 = max(1, e + 1 - N);
                const int o1 = pb + doff[e + 1] - jmin1;
                if (i + 1 <= N)  // child (i+1, j): we are its up-parent
                    Eij += Eb[p1][j] * g_wu[o1 + j];
                if (j + 1 <= N)  // child (i, j+1): we are its left-parent
                    Eij += Eb[p1][j + 1] * g_wl[o1 + j + 1];
                if (i + 1 <= N && j + 1 <= N) {  // child (i+1,j+1): diag parent
                    const int jmin2 = max(1, e + 2 - N);
                    Eij += Eb[p2][j + 1] * g_wd[pb + doff[e + 2] - jmin2 + j + 1];
                }
            }
            Eb[cur][j] = Eij;
            const float dd = (float)(i - j);
            acc += Eij * dd * dd;
        }
        __syncthreads();
    }

    // block reduction of temporal accumulator
    for (int o = 16; o; o >>= 1)
        acc += __shfl_down_sync(0xffffffffu, acc, o);
    if ((tid & 31) == 0) warp_sum[tid >> 5] = acc;
    __syncthreads();
    if (tid == 0) {
        float tot = 0.0f;
#pragma unroll
        for (int w = 0; w < 5; ++w) tot += warp_sum[w];
        g_lt[prob] = tot * (1.0f / (float)NCELLS);
        g_sdtw[prob] = s_sdtw;
    }
}

__global__ __launch_bounds__(BATCH) void dtw_reduce_kernel(
    float* __restrict__ out) {
    __shared__ float sh[BATCH];
    const int b = threadIdx.x;
    float ls = 0.0f, lt = 0.0f;
#pragma unroll
    for (int c = 0; c < CH; ++c) {
        ls += g_sdtw[b * CH + c];
        lt += g_lt[b * CH + c];
    }
    ls *= (1.0f / (float)CH);
    lt *= (1.0f / (float)CH);
    out[1 + b] = ls;              // loss_shape
    out[1 + BATCH + b] = lt;      // loss_temporal
    sh[b] = 0.5f * ls + 0.5f * lt;
    __syncthreads();
    if (b == 0) {
        float tot = 0.0f;
#pragma unroll
        for (int k = 0; k < BATCH; ++k) tot += sh[k];
        out[0] = tot * (1.0f / (float)BATCH);  // loss
    }
}

extern "C" void kernel_launch(void* const* d_in, const int* in_sizes, int n_in,
                              void* d_out, int out_size) {
    const float* input = (const float*)d_in[0];
    const float* target = (const float*)d_in[1];
    float* out = (float*)d_out;
    dtw_fwd_bwd_kernel<<<BC, 160>>>(input, target);
    dtw_reduce_kernel<<<1, BATCH>>>(out);
}

// round 9
// speedup vs baseline: 1.3068x; 1.3068x over previous
#include <cuda_runtime.h>

#define N 160
#define NCELLS (N * N)
#define NDIAG (2 * N - 1)  // 319 anti-diagonals, 0-based s = ri + c
#define BC 512
#define CH 8
#define BATCH 64
#define BIGV 1e10f
#define GAMMA 0.01f
#define INVG 100.0f
#define FULLM 0xffffffffu

// Softmin gradient weights per cell, diag-major compacted, SoA (coalesced).
__device__ float g_wd[(size_t)BC * NCELLS];  // diag-parent weight
__device__ float g_wu[(size_t)BC * NCELLS];  // up-parent weight
__device__ float g_wl[(size_t)BC * NCELLS];  // left-parent weight
__device__ float g_sdtw[BC];
__device__ float g_lt[BC];

// cells preceding 0-based anti-diagonal s
__device__ __forceinline__ int doffs(int s) {
    return (s <= 160) ? (s * (s + 1)) / 2
                      : NCELLS - ((319 - s) * (320 - s)) / 2;
}

__global__ __launch_bounds__(128) void dtw_warp_kernel(
    const float* __restrict__ input, const float* __restrict__ target) {
    const int lane = threadIdx.x & 31;
    const int w = threadIdx.x >> 5;
    const int prob = blockIdx.x * 4 + w;  // 1 warp = 1 problem

    __shared__ float sp_s[4][N];
    __shared__ int doffT[NDIAG + 2];  // indices 0..320 (319,320 zero pad)

    for (int k = threadIdx.x; k < NDIAG + 2; k += 128)
        doffT[k] = (k < NDIAG) ? doffs(k) : 0;
    for (int k = lane; k < N; k += 32) sp_s[w][k] = input[prob * N + k];
    float st5[5];
#pragma unroll
    for (int g = 0; g < 5; ++g) st5[g] = target[prob * N + lane + 32 * g];
    __syncthreads();

    const int pb = prob * NCELLS;
    float Rcur[5], uprev[5];
#pragma unroll
    for (int g = 0; g < 5; ++g) { Rcur[g] = BIGV; uprev[g] = BIGV; }

    // ---------------- forward: shuffle-synchronized wavefront ----------------
    // thread `lane` owns cell rows ri = lane + 32g; at step s it handles
    // column c = s - ri (if 0 <= c < N). Row ri-1 values come from lane-1
    // (or lane 31, group g-1, for lane 0) one step delayed.
    for (int s = 0; s < NDIAG; ++s) {
        float u[5];
#pragma unroll
        for (int g = 0; g < 5; ++g)
            u[g] = __shfl_sync(FULLM, Rcur[g], (lane + 31) & 31);
        const int dof = doffT[s];
        const int rmin = max(0, s - (N - 1));
#pragma unroll
        for (int g = 0; g < 5; ++g) {
            const int ri = lane + 32 * g;
            const int c = s - ri;
            if (c < 0 || c >= N) continue;
            const float uu = (lane == 0) ? ((g == 0) ? BIGV : u[g - 1]) : u[g];
            // upper = R[ri-1][c]; DP row 0 is the BIG border (except R[0][0])
            const float upv = (ri == 0) ? BIGV : uu;
            const float dg = (c == 0) ? ((ri == 0) ? 0.0f : BIGV)
                                      : ((ri == 0) ? BIGV : uprev[g]);
            const float lf = (c == 0) ? BIGV : Rcur[g];
            float d = st5[g] - sp_s[w][c];
            d *= d;
            const float mn = fminf(dg, fminf(upv, lf));
            const float ea = __expf((mn - dg) * INVG);
            const float eb = __expf((mn - upv) * INVG);
            const float ec = __expf((mn - lf) * INVG);
            const float ssum = ea + eb + ec;
            const float r = d + mn - GAMMA * __logf(ssum);
            const float inv = __fdividef(1.0f, ssum);
            const int o = pb + dof + (ri - rmin);
            g_wd[o] = ea * inv;
            g_wu[o] = eb * inv;
            g_wl[o] = ec * inv;
            uprev[g] = upv;  // becomes R[ri-1][c] = next step's diag parent
            Rcur[g] = r;
        }
    }
    if (lane == 31) g_sdtw[prob] = Rcur[4];  // R[N][N]

    // ---------------- backward: reverse wavefront, prefetched weights -------
    float Ecur[5], dprev[5];
#pragma unroll
    for (int g = 0; g < 5; ++g) { Ecur[g] = 0.0f; dprev[g] = 0.0f; }
    float acc = 0.0f;

    float wuA[5], wlA[5], wdA[5];
    auto fetchW = [&](int sbq, float* fu, float* fl, float* fd) {
        const int d1 = doffT[sbq + 1];
        const int d2 = doffT[sbq + 2];
        const int rm1 = max(0, sbq + 1 - (N - 1));
        const int rm2 = max(0, sbq + 2 - (N - 1));
#pragma unroll
        for (int g = 0; g < 5; ++g) {
            const int ri = lane + 32 * g;
            const int c = sbq - ri;
            if (c < 0 || c >= N) continue;
            if (ri + 1 < N) {
                fu[g] = g_wu[pb + d1 + (ri + 1 - rm1)];
                if (c + 1 < N) fd[g] = g_wd[pb + d2 + (ri + 1 - rm2)];
            }
            if (c + 1 < N) fl[g] = g_wl[pb + d1 + (ri - rm1)];
        }
    };
    fetchW(NDIAG - 1, wuA, wlA, wdA);

    for (int sb = NDIAG - 1; sb >= 0; --sb) {
        float wuB[5], wlB[5], wdB[5];
        if (sb > 0) fetchW(sb - 1, wuB, wlB, wdB);  // prefetch next diagonal
        float sd[5];
#pragma unroll
        for (int g = 0; g < 5; ++g)
            sd[g] = __shfl_sync(FULLM, Ecur[g], (lane + 1) & 31);
#pragma unroll
        for (int g = 0; g < 5; ++g) {
            const int ri = lane + 32 * g;
            const int c = sb - ri;
            if (c < 0 || c >= N) continue;
            float ev;
            if (sb == NDIAG - 1) {
                ev = 1.0f;  // seed E[N][N]
            } else {
                // E of child (ri+1, c): lane+1's previous value
                const float echild =
                    (lane < 31) ? sd[g] : ((g < 4) ? sd[g + 1] : 0.0f);
                ev = 0.0f;
                if (ri + 1 < N) {
                    ev += echild * wuA[g];
                    if (c + 1 < N) ev += dprev[g] * wdA[g];
                }
                if (c + 1 < N) ev += Ecur[g] * wlA[g];  // child (ri, c+1) = own prev
                dprev[g] = echild;  // becomes (ri+1, c+1) child next iteration
            }
            Ecur[g] = ev;
            const float dd = (float)(ri - c);  // (i - j) in DP indices
            acc += ev * dd * dd;
        }
#pragma unroll
        for (int g = 0; g < 5; ++g) {
            wuA[g] = wuB[g];
            wlA[g] = wlB[g];
            wdA[g] = wdB[g];
        }
    }

    // warp reduction of temporal accumulator
#pragma unroll
    for (int o = 16; o; o >>= 1) acc += __shfl_down_sync(FULLM, acc, o);
    if (lane == 0) g_lt[prob] = acc * (1.0f / (float)NCELLS);
}

__global__ __launch_bounds__(BATCH) void dtw_reduce_kernel(
    float* __restrict__ out) {
    __shared__ float sh[BATCH];
    const int b = threadIdx.x;
    float ls = 0.0f, lt = 0.0f;
#pragma unroll
    for (int c = 0; c < CH; ++c) {
        ls += g_sdtw[b * CH + c];
        lt += g_lt[b * CH + c];
    }
    ls *= (1.0f / (float)CH);
    lt *= (1.0f / (float)CH);
    out[1 + b] = ls;          // loss_shape
    out[1 + BATCH + b] = lt;  // loss_temporal
    sh[b] = 0.5f * ls + 0.5f * lt;
    __syncthreads();
    if (b == 0) {
        float tot = 0.0f;
#pragma unroll
        for (int k = 0; k < BATCH; ++k) tot += sh[k];
        out[0] = tot * (1.0f / (float)BATCH);  // loss
    }
}

extern "C" void kernel_launch(void* const* d_in, const int* in_sizes, int n_in,
                              void* d_out, int out_size) {
    const float* input = (const float*)d_in[0];
    const float* target = (const float*)d_in[1];
    float* out = (float*)d_out;
    dtw_warp_kernel<<<BC / 4, 128>>>(input, target);
    dtw_reduce_kernel<<<1, BATCH>>>(out);
}

// round 10
// speedup vs baseline: 1.7549x; 1.3429x over previous
#include <cuda_runtime.h>
#include <cstdint>

#define N 160
#define NCELLS (N * N)
#define NDIAG (2 * N - 1)  // 319 anti-diagonals, 0-based s = ri + c
#define BC 512
#define CH 8
#define BATCH 64
#define BIGV 1e10f
#define GAMMA 0.01f
#define INVG 100.0f
#define FULLM 0xffffffffu

// Softmin gradient weights per cell: (wd, wu) packed; wl = 1 - wd - wu.
// Diag-major compacted. +256 cells padding so fixed-size 1280B diagonal
// prefetches can safely overrun the last chunk.
__device__ float2 g_w2[(size_t)BC * NCELLS + 256];
__device__ float g_sdtw[BC];
__device__ float g_lt[BC];

// cells preceding 0-based anti-diagonal s
__device__ __forceinline__ int doffs(int s) {
    return (s <= 160) ? (s * (s + 1)) / 2
                      : NCELLS - ((319 - s) * (320 - s)) / 2;
}

__device__ __forceinline__ uint32_t smem_u32(const void* p) {
    return (uint32_t)__cvta_generic_to_shared(p);
}
__device__ __forceinline__ void cpa8(uint32_t dst, const void* src) {
    asm volatile("cp.async.ca.shared.global [%0], [%1], 8;" ::"r"(dst),
                 "l"(src));
}
#define CP_COMMIT() asm volatile("cp.async.commit_group;" ::: "memory")
#define CP_WAIT6() asm volatile("cp.async.wait_group 6;" ::: "memory")

__global__ __launch_bounds__(128) void dtw_warp_kernel(
    const float* __restrict__ input, const float* __restrict__ target) {
    const int lane = threadIdx.x & 31;
    const int w = threadIdx.x >> 5;
    const int prob = blockIdx.x * 4 + w;  // 1 warp = 1 problem

    __shared__ float sp_s[4][N];
    __shared__ float2 ring[4][8][N];  // per-warp 8-slot diagonal ring (40KB)
    __shared__ int doffT[NDIAG + 2];

    for (int k = threadIdx.x; k < NDIAG + 2; k += 128)
        doffT[k] = (k < NDIAG) ? doffs(k) : 0;
    for (int k = lane; k < N; k += 32) sp_s[w][k] = input[prob * N + k];
    float st5[5];
#pragma unroll
    for (int g = 0; g < 5; ++g) st5[g] = target[prob * N + lane + 32 * g];
    __syncthreads();

    const int pb = prob * NCELLS;
    float Rcur[5], uprev[5];
#pragma unroll
    for (int g = 0; g < 5; ++g) { Rcur[g] = BIGV; uprev[g] = BIGV; }

    // ---------------- forward: shuffle-synchronized wavefront ----------------
    for (int s = 0; s < NDIAG; ++s) {
        float u[5];
#pragma unroll
        for (int g = 0; g < 5; ++g)
            u[g] = __shfl_sync(FULLM, Rcur[g], (lane + 31) & 31);
        const int dof = doffT[s];
        const int rmin = max(0, s - (N - 1));
#pragma unroll
        for (int g = 0; g < 5; ++g) {
            const int ri = lane + 32 * g;
            const int c = s - ri;
            if (c < 0 || c >= N) continue;
            const float uu = (lane == 0) ? ((g == 0) ? BIGV : u[g - 1]) : u[g];
            const float upv = (ri == 0) ? BIGV : uu;
            const float dg = (c == 0) ? ((ri == 0) ? 0.0f : BIGV)
                                      : ((ri == 0) ? BIGV : uprev[g]);
            const float lf = (c == 0) ? BIGV : Rcur[g];
            float d = st5[g] - sp_s[w][c];
            d *= d;
            const float mn = fminf(dg, fminf(upv, lf));
            const float ea = __expf((mn - dg) * INVG);
            const float eb = __expf((mn - upv) * INVG);
            const float ec = __expf((mn - lf) * INVG);
            const float ssum = ea + eb + ec;
            const float r = d + mn - GAMMA * __logf(ssum);
            const float inv = __fdividef(1.0f, ssum);
            g_w2[pb + dof + (ri - rmin)] = make_float2(ea * inv, eb * inv);
            uprev[g] = upv;
            Rcur[g] = r;
        }
    }
    if (lane == 31) g_sdtw[prob] = Rcur[4];  // R[N-1][N-1]

    __threadfence_block();  // order weight stores before cp.async readback

    // ---------------- backward: reverse wavefront, cp.async-staged weights ---
    // diag d staged into ring slot d&7; diag d is prefetched at end of
    // iteration d+6 and first read at iteration d-1 (as sb+1).
    auto prefetch = [&](int d) {
        const float2* src = g_w2 + pb + doffT[d] + lane;
        uint32_t dst = smem_u32(&ring[w][d & 7][lane]);
#pragma unroll
        for (int k = 0; k < 5; ++k)
            cpa8(dst + (uint32_t)(k * 32 * sizeof(float2)), src + k * 32);
        CP_COMMIT();
    };
#pragma unroll
    for (int d = NDIAG - 1; d >= NDIAG - 6; --d) prefetch(d);  // 318..313

    float Ecur[5], dprev[5];
#pragma unroll
    for (int g = 0; g < 5; ++g) { Ecur[g] = 0.0f; dprev[g] = 0.0f; }
    float acc = 0.0f;

    for (int sb = NDIAG - 1; sb >= 0; --sb) {
        CP_WAIT6();  // guarantees diag sb+1 (and older) staged
        float sd[5];
#pragma unroll
        for (int g = 0; g < 5; ++g)
            sd[g] = __shfl_sync(FULLM, Ecur[g], (lane + 1) & 31);
        const float2* ch1 = ring[w][(sb + 1) & 7];
        const float2* ch2 = ring[w][(sb + 2) & 7];
        const int rm1 = max(0, sb + 1 - (N - 1));
        const int rm2 = max(0, sb + 2 - (N - 1));
#pragma unroll
        for (int g = 0; g < 5; ++g) {
            const int ri = lane + 32 * g;
            const int c = sb - ri;
            if (c < 0 || c >= N) continue;
            float ev;
            if (sb == NDIAG - 1) {
                ev = 1.0f;  // seed E[N-1][N-1]
            } else {
                const float echild =
                    (lane < 31) ? sd[g] : ((g < 4) ? sd[g + 1] : 0.0f);
                ev = 0.0f;
                if (ri + 1 < N) {  // child (ri+1, c): its wu
                    const float2 f = ch1[ri + 1 - rm1];
                    ev += echild * f.y;
                    if (c + 1 < N) {  // child (ri+1, c+1): its wd
                        const float2 h = ch2[ri + 1 - rm2];
                        ev += dprev[g] * h.x;
                    }
                }
                if (c + 1 < N) {  // child (ri, c+1): its wl = 1-wd-wu
                    const float2 q = ch1[ri - rm1];
                    ev += Ecur[g] * (1.0f - q.x - q.y);
                }
                dprev[g] = echild;
            }
            Ecur[g] = ev;
            const float dd = (float)(ri - c);
            acc += ev * dd * dd;
        }
        const int pf = sb - 6;
        if (pf >= 0) prefetch(pf);
    }

    // warp reduction of temporal accumulator
#pragma unroll
    for (int o = 16; o; o >>= 1) acc += __shfl_down_sync(FULLM, acc, o);
    if (lane == 0) g_lt[prob] = acc * (1.0f / (float)NCELLS);
}

__global__ __launch_bounds__(BATCH) void dtw_reduce_kernel(
    float* __restrict__ out) {
    __shared__ float sh[BATCH];
    const int b = threadIdx.x;
    float ls = 0.0f, lt = 0.0f;
#pragma unroll
    for (int c = 0; c < CH; ++c) {
        ls += g_sdtw[b * CH + c];
        lt += g_lt[b * CH + c];
    }
    ls *= (1.0f / (float)CH);
    lt *= (1.0f / (float)CH);
    out[1 + b] = ls;          // loss_shape
    out[1 + BATCH + b] = lt;  // loss_temporal
    sh[b] = 0.5f * ls + 0.5f * lt;
    __syncthreads();
    if (b == 0) {
        float tot = 0.0f;
#pragma unroll
        for (int k = 0; k < BATCH; ++k) tot += sh[k];
        out[0] = tot * (1.0f / (float)BATCH);  // loss
    }
}

extern "C" void kernel_launch(void* const* d_in, const int* in_sizes, int n_in,
                              void* d_out, int out_size) {
    const float* input = (const float*)d_in[0];
    const float* target = (const float*)d_in[1];
    float* out = (float*)d_out;
    dtw_warp_kernel<<<BC / 4, 128>>>(input, target);
    dtw_reduce_kernel<<<1, BATCH>>>(out);
}